// round 3
// baseline (speedup 1.0000x reference)
#include <cuda_runtime.h>

// LightGCN_4440996184480 — structural simplification (verified rel_err=0):
// norm == 0 for all edges (user nodes have zero in-degree => dis[src]=0),
// so all GCN propagation layers are exactly zero.
//   out[0 : 32M)     = user_emb * 0.25
//   out[32M : 44.8M) = (audio + artist_emb[aid] + album_emb[alid]) * 0.25
//   out[44.8M]       = mean((item_h/4 - audio @ W^T)^2)
//
// R3: shuffle-free dot product (smem broadcast LDS + register W row),
// single-wave persistent grid: 152 item blocks + 152 user blocks co-resident
// (occupancy 2) so FFMA work and DRAM copy overlap.

#define NUM_USERS  500000
#define NUM_ITEMS  200000
#define EMBED_DIM  64
#define USER_ELEMS (NUM_USERS * EMBED_DIM)   // 32,000,000
#define ITEM_ELEMS (NUM_ITEMS * EMBED_DIM)   // 12,800,000
#define LOSS_IDX   (USER_ELEMS + ITEM_ELEMS) // 44,800,000

#define ITEM_BLOCKS 152
#define USER_BLOCKS 152
#define TOTAL_BLOCKS (ITEM_BLOCKS + USER_BLOCKS)
#define NUM_STREAMS  (ITEM_BLOCKS * 4)       // 608 item streams (2 warps each)
#define NUM_PARTIALS (ITEM_BLOCKS * 8)

__device__ float g_partials[NUM_PARTIALS];

__global__ __launch_bounds__(256, 2) void fused_kernel(
    const float* __restrict__ user_emb,
    const float* __restrict__ artist_emb,
    const float* __restrict__ album_emb,
    const float* __restrict__ audio,
    const float* __restrict__ Wproj,       // (64,64) row-major: proj[j]=dot(a, W[j,:])
    const int*   __restrict__ artist_ids,
    const int*   __restrict__ album_ids,
    float*       __restrict__ out)
{
    if (blockIdx.x < ITEM_BLOCKS) {
        // ---------------- item path: warp-autonomous, barrier-free ----------
        __shared__ float sh[8][64];            // per-warp private audio row

        const int tid    = threadIdx.x;
        const int warp   = tid >> 5;
        const int lane   = tid & 31;
        const int h      = warp & 1;                       // column half
        const int stream = blockIdx.x * 4 + (warp >> 1);   // item stream
        const int j      = h * 32 + lane;                  // owned column

        // W row j register-resident (all accesses below fully unrolled)
        float w[64];
        #pragma unroll
        for (int q = 0; q < 16; ++q) {
            float4 v = reinterpret_cast<const float4*>(Wproj)[j * 16 + q];
            w[4*q+0] = v.x; w[4*q+1] = v.y; w[4*q+2] = v.z; w[4*q+3] = v.w;
        }

        float  lsum = 0.0f;
        float* item_out = out + USER_ELEMS;
        const float4* shv = reinterpret_cast<const float4*>(sh[warp]);

        int item = stream;
        int idxA = 0, idxB = 0;
        if (item < NUM_ITEMS) { idxA = artist_ids[item]; idxB = album_ids[item]; }

        while (item < NUM_ITEMS) {
            // front-batched loads: audio row halves + gathered rows
            const float a_lo = audio[item * 64 + lane];
            const float a_hi = audio[item * 64 + 32 + lane];
            const float ar   = artist_emb[idxA * 64 + j];
            const float al   = album_emb [idxB * 64 + j];

            const int nitem = item + NUM_STREAMS;
            if (nitem < NUM_ITEMS) {                       // prefetch indices
                idxA = artist_ids[nitem];
                idxB = album_ids [nitem];
            }

            __syncwarp();                 // prior iter's LDS done before STS
            sh[warp][lane]      = a_lo;
            sh[warp][32 + lane] = a_hi;
            __syncwarp();                 // STS visible before LDS

            // proj[j] = dot(audio_row, W[j,:]) — broadcast LDS.128 + FFMA
            float s0 = 0.f, s1 = 0.f, s2 = 0.f, s3 = 0.f;
            #pragma unroll
            for (int q = 0; q < 16; ++q) {
                const float4 av = shv[q];
                s0 = fmaf(av.x, w[4*q+0], s0);
                s1 = fmaf(av.y, w[4*q+1], s1);
                s2 = fmaf(av.z, w[4*q+2], s2);
                s3 = fmaf(av.w, w[4*q+3], s3);
            }

            const float a_own = h ? a_hi : a_lo;
            const float d     = (a_own + ar + al) * 0.25f;
            item_out[item * 64 + j] = d;

            const float diff = d - ((s0 + s1) + (s2 + s3));
            lsum += diff * diff;

            item = nitem;
        }

        // deterministic warp reduction
        #pragma unroll
        for (int off = 16; off > 0; off >>= 1)
            lsum += __shfl_xor_sync(0xffffffffu, lsum, off);
        if (lane == 0)
            g_partials[blockIdx.x * 8 + warp] = lsum;
    } else {
        // ---------------- user path: scale-copy 32M floats, MLP >= 4 --------
        const float4* in4  = reinterpret_cast<const float4*>(user_emb);
        float4*       out4 = reinterpret_cast<float4*>(out);
        const int n4     = USER_ELEMS / 4;                 // 8,000,000
        const int bid    = blockIdx.x - ITEM_BLOCKS;
        const int stride = USER_BLOCKS * 256;              // 38,912
        int i = bid * 256 + threadIdx.x;

        // main: 4 independent float4 round-trips in flight per thread
        for (; i + 3 * stride < n4; i += 4 * stride) {
            float4 v0 = in4[i];
            float4 v1 = in4[i +     stride];
            float4 v2 = in4[i + 2 * stride];
            float4 v3 = in4[i + 3 * stride];
            v0.x *= 0.25f; v0.y *= 0.25f; v0.z *= 0.25f; v0.w *= 0.25f;
            v1.x *= 0.25f; v1.y *= 0.25f; v1.z *= 0.25f; v1.w *= 0.25f;
            v2.x *= 0.25f; v2.y *= 0.25f; v2.z *= 0.25f; v2.w *= 0.25f;
            v3.x *= 0.25f; v3.y *= 0.25f; v3.z *= 0.25f; v3.w *= 0.25f;
            out4[i]              = v0;
            out4[i +     stride] = v1;
            out4[i + 2 * stride] = v2;
            out4[i + 3 * stride] = v3;
        }
        for (; i < n4; i += stride) {
            float4 v = in4[i];
            v.x *= 0.25f; v.y *= 0.25f; v.z *= 0.25f; v.w *= 0.25f;
            out4[i] = v;
        }
    }
}

__global__ void finalize_kernel(float* __restrict__ out)
{
    __shared__ float red[256];
    float s = 0.0f;
    for (int i = threadIdx.x; i < NUM_PARTIALS; i += 256) s += g_partials[i];
    red[threadIdx.x] = s;
    __syncthreads();
    #pragma unroll
    for (int off = 128; off > 0; off >>= 1) {
        if (threadIdx.x < off) red[threadIdx.x] += red[threadIdx.x + off];
        __syncthreads();
    }
    if (threadIdx.x == 0)
        out[LOSS_IDX] = red[0] * (1.0f / (float)ITEM_ELEMS);
}

extern "C" void kernel_launch(void* const* d_in, const int* in_sizes, int n_in,
                              void* d_out, int out_size)
{
    const float* user_emb   = (const float*)d_in[0];
    const float* artist_emb = (const float*)d_in[1];
    const float* album_emb  = (const float*)d_in[2];
    const float* audio      = (const float*)d_in[3];
    const float* Wproj      = (const float*)d_in[4];
    // d_in[5..11]: mlp weights / edge data — dead (norm == 0 structurally)
    const int* artist_ids   = (const int*)d_in[12];
    const int* album_ids    = (const int*)d_in[13];
    float* out = (float*)d_out;

    fused_kernel<<<TOTAL_BLOCKS, 256>>>(user_emb, artist_emb, album_emb, audio,
                                        Wproj, artist_ids, album_ids, out);
    finalize_kernel<<<1, 256>>>(out);
}

// round 4
// speedup vs baseline: 1.3754x; 1.3754x over previous
#include <cuda_runtime.h>

// LightGCN_4440996184480 — structural simplification (verified rel_err=0):
// norm == 0 for all edges (user nodes have zero in-degree => dis[src]=0),
// so all GCN propagation layers are exactly zero.
//   out[0 : 32M)     = user_emb * 0.25
//   out[32M : 44.8M) = (audio + artist_emb[aid] + album_emb[alid]) * 0.25
//   out[44.8M]       = mean((item_h/4 - audio @ W^T)^2)
//
// R4: wide grid (high TLP for gather latency) + shuffle-free smem-broadcast
// dot + parity-interleaved block classes (item/user co-resident every wave)
// + 2 items per warp-iteration (12 independent loads in flight).

#define NUM_USERS  500000
#define NUM_ITEMS  200000
#define EMBED_DIM  64
#define USER_ELEMS (NUM_USERS * EMBED_DIM)   // 32,000,000
#define ITEM_ELEMS (NUM_ITEMS * EMBED_DIM)   // 12,800,000
#define LOSS_IDX   (USER_ELEMS + ITEM_ELEMS) // 44,800,000

#define ITEM_BLOCKS 592
#define USER_BLOCKS 592
#define TOTAL_BLOCKS (ITEM_BLOCKS + USER_BLOCKS)
#define NUM_STREAMS  (ITEM_BLOCKS * 4)       // 2368 item streams (2 warps each)
#define NUM_PARTIALS (ITEM_BLOCKS * 8)

__device__ float g_partials[NUM_PARTIALS];

__global__ __launch_bounds__(256) void fused_kernel(
    const float* __restrict__ user_emb,
    const float* __restrict__ artist_emb,
    const float* __restrict__ album_emb,
    const float* __restrict__ audio,
    const float* __restrict__ Wproj,       // (64,64) row-major: proj[j]=dot(a, W[j,:])
    const int*   __restrict__ artist_ids,
    const int*   __restrict__ album_ids,
    float*       __restrict__ out)
{
    // parity-interleaved classes: even block = item path, odd block = user copy
    if ((blockIdx.x & 1) == 0) {
        // ---------------- item path: warp-autonomous, barrier-free ----------
        __shared__ float sh[8][128];           // per-warp: 2 item rows

        const int ibid   = blockIdx.x >> 1;                // 0..591
        const int tid    = threadIdx.x;
        const int warp   = tid >> 5;
        const int lane   = tid & 31;
        const int h      = warp & 1;                       // column half
        const int stream = ibid * 4 + (warp >> 1);         // item stream
        const int j      = h * 32 + lane;                  // owned column

        // W row j register-resident
        float w[64];
        #pragma unroll
        for (int q = 0; q < 16; ++q) {
            float4 v = reinterpret_cast<const float4*>(Wproj)[j * 16 + q];
            w[4*q+0] = v.x; w[4*q+1] = v.y; w[4*q+2] = v.z; w[4*q+3] = v.w;
        }

        float  lsum = 0.0f;
        float* item_out = out + USER_ELEMS;
        const float4* shv = reinterpret_cast<const float4*>(sh[warp]);

        int item = stream;
        int idxA1 = 0, idxB1 = 0, idxA2 = 0, idxB2 = 0;
        {
            const int i2 = item + NUM_STREAMS;
            if (item < NUM_ITEMS) { idxA1 = artist_ids[item]; idxB1 = album_ids[item]; }
            if (i2   < NUM_ITEMS) { idxA2 = artist_ids[i2];   idxB2 = album_ids[i2]; }
        }

        while (item < NUM_ITEMS) {
            const int item2 = item + NUM_STREAMS;
            const bool has2 = (item2 < NUM_ITEMS);

            // front-batched independent loads (gathers fly together)
            const float a_lo1 = audio[item * 64 + lane];
            const float a_hi1 = audio[item * 64 + 32 + lane];
            const float ar1   = artist_emb[idxA1 * 64 + j];
            const float al1   = album_emb [idxB1 * 64 + j];
            float a_lo2 = 0.f, a_hi2 = 0.f, ar2 = 0.f, al2 = 0.f;
            if (has2) {
                a_lo2 = audio[item2 * 64 + lane];
                a_hi2 = audio[item2 * 64 + 32 + lane];
                ar2   = artist_emb[idxA2 * 64 + j];
                al2   = album_emb [idxB2 * 64 + j];
            }

            // prefetch next pair's indices
            const int nitem  = item + 2 * NUM_STREAMS;
            const int nitem2 = nitem + NUM_STREAMS;
            if (nitem  < NUM_ITEMS) { idxA1 = artist_ids[nitem];  idxB1 = album_ids[nitem]; }
            if (nitem2 < NUM_ITEMS) { idxA2 = artist_ids[nitem2]; idxB2 = album_ids[nitem2]; }

            __syncwarp();                 // prior iter's LDS done before STS
            sh[warp][lane]       = a_lo1;
            sh[warp][32 + lane]  = a_hi1;
            sh[warp][64 + lane]  = a_lo2;
            sh[warp][96 + lane]  = a_hi2;
            __syncwarp();                 // STS visible before LDS

            // both dots: broadcast LDS.128 + register W
            float s0 = 0.f, s1 = 0.f, s2 = 0.f, s3 = 0.f;
            float t0 = 0.f, t1 = 0.f, t2 = 0.f, t3 = 0.f;
            #pragma unroll
            for (int q = 0; q < 16; ++q) {
                const float4 av = shv[q];
                const float4 bv = shv[16 + q];
                s0 = fmaf(av.x, w[4*q+0], s0);
                s1 = fmaf(av.y, w[4*q+1], s1);
                s2 = fmaf(av.z, w[4*q+2], s2);
                s3 = fmaf(av.w, w[4*q+3], s3);
                t0 = fmaf(bv.x, w[4*q+0], t0);
                t1 = fmaf(bv.y, w[4*q+1], t1);
                t2 = fmaf(bv.z, w[4*q+2], t2);
                t3 = fmaf(bv.w, w[4*q+3], t3);
            }

            {
                const float a_own = h ? a_hi1 : a_lo1;
                const float d     = (a_own + ar1 + al1) * 0.25f;
                item_out[item * 64 + j] = d;
                const float diff = d - ((s0 + s1) + (s2 + s3));
                lsum = fmaf(diff, diff, lsum);
            }
            if (has2) {
                const float a_own = h ? a_hi2 : a_lo2;
                const float d     = (a_own + ar2 + al2) * 0.25f;
                item_out[item2 * 64 + j] = d;
                const float diff = d - ((t0 + t1) + (t2 + t3));
                lsum = fmaf(diff, diff, lsum);
            }

            item = nitem;
        }

        // deterministic warp reduction
        #pragma unroll
        for (int off = 16; off > 0; off >>= 1)
            lsum += __shfl_xor_sync(0xffffffffu, lsum, off);
        if (lane == 0)
            g_partials[ibid * 8 + warp] = lsum;
    } else {
        // ---------------- user path: scale-copy 32M floats ------------------
        const float4* in4  = reinterpret_cast<const float4*>(user_emb);
        float4*       out4 = reinterpret_cast<float4*>(out);
        const int n4     = USER_ELEMS / 4;                 // 8,000,000
        const int ubid   = blockIdx.x >> 1;                // 0..591
        const int stride = USER_BLOCKS * 256;
        for (int i = ubid * 256 + threadIdx.x; i < n4; i += stride) {
            float4 v = in4[i];
            v.x *= 0.25f; v.y *= 0.25f; v.z *= 0.25f; v.w *= 0.25f;
            out4[i] = v;
        }
    }
}

__global__ void finalize_kernel(float* __restrict__ out)
{
    __shared__ float red[256];
    float s = 0.0f;
    for (int i = threadIdx.x; i < NUM_PARTIALS; i += 256) s += g_partials[i];
    red[threadIdx.x] = s;
    __syncthreads();
    #pragma unroll
    for (int off = 128; off > 0; off >>= 1) {
        if (threadIdx.x < off) red[threadIdx.x] += red[threadIdx.x + off];
        __syncthreads();
    }
    if (threadIdx.x == 0)
        out[LOSS_IDX] = red[0] * (1.0f / (float)ITEM_ELEMS);
}

extern "C" void kernel_launch(void* const* d_in, const int* in_sizes, int n_in,
                              void* d_out, int out_size)
{
    const float* user_emb   = (const float*)d_in[0];
    const float* artist_emb = (const float*)d_in[1];
    const float* album_emb  = (const float*)d_in[2];
    const float* audio      = (const float*)d_in[3];
    const float* Wproj      = (const float*)d_in[4];
    // d_in[5..11]: mlp weights / edge data — dead (norm == 0 structurally)
    const int* artist_ids   = (const int*)d_in[12];
    const int* album_ids    = (const int*)d_in[13];
    float* out = (float*)d_out;

    fused_kernel<<<TOTAL_BLOCKS, 256>>>(user_emb, artist_emb, album_emb, audio,
                                        Wproj, artist_ids, album_ids, out);
    finalize_kernel<<<1, 256>>>(out);
}

// round 5
// speedup vs baseline: 1.3855x; 1.0074x over previous
#include <cuda_runtime.h>

// LightGCN_4440996184480 — structural simplification (verified rel_err=0):
// norm == 0 for all edges (user nodes have zero in-degree => dis[src]=0),
// so all GCN propagation layers are exactly zero.
//   out[0 : 32M)     = user_emb * 0.25
//   out[32M : 44.8M) = (audio + artist_emb[aid] + album_emb[alid]) * 0.25
//   out[44.8M]       = mean((item_h/4 - audio @ W^T)^2)
//
// R5: item path as smem-tiled scalar GEMM (W in smem, ~40 regs/thread,
// high occupancy) + parity-interleaved DRAM-bound user-copy blocks.

#define NUM_USERS  500000
#define NUM_ITEMS  200000
#define EMBED_DIM  64
#define USER_ELEMS (NUM_USERS * EMBED_DIM)   // 32,000,000
#define ITEM_ELEMS (NUM_ITEMS * EMBED_DIM)   // 12,800,000
#define LOSS_IDX   (USER_ELEMS + ITEM_ELEMS) // 44,800,000

#define ITEM_BLOCKS 304
#define USER_BLOCKS 304
#define TOTAL_BLOCKS (ITEM_BLOCKS + USER_BLOCKS)
#define TILE_I 32                             // items per tile
#define PITCH 68                              // smem row pitch (floats)

__device__ float g_partials[ITEM_BLOCKS];

__global__ __launch_bounds__(256) void fused_kernel(
    const float* __restrict__ user_emb,
    const float* __restrict__ artist_emb,
    const float* __restrict__ album_emb,
    const float* __restrict__ audio,
    const float* __restrict__ Wproj,       // (64,64) row-major: proj[j]=dot(a, W[j,:])
    const int*   __restrict__ artist_ids,
    const int*   __restrict__ album_ids,
    float*       __restrict__ out)
{
    __shared__ float w_s[64][PITCH];       // W rows, padded
    __shared__ float a_s[TILE_I][PITCH];   // audio tile, padded
    __shared__ int   aid_s[TILE_I];
    __shared__ int   alid_s[TILE_I];
    __shared__ float red[256];

    const int tid = threadIdx.x;

    if ((blockIdx.x & 1) == 0) {
        // ---------------- item path: tiled scalar GEMM + fused epilogue -----
        const int ibid = blockIdx.x >> 1;  // 0..303
        const int j    = tid & 63;         // owned output column
        const int g    = tid >> 6;         // item group (0..3): items 8g..8g+7

        // stage W into smem (once per block), coalesced
        #pragma unroll
        for (int r = 0; r < 16; ++r) {
            const int e = tid + 256 * r;          // 0..4095
            w_s[e >> 6][e & 63] = Wproj[e];
        }
        __syncthreads();

        float  lsum = 0.0f;
        float* item_out = out + USER_ELEMS;

        for (int base = ibid * TILE_I; base < NUM_ITEMS; base += ITEM_BLOCKS * TILE_I) {
            __syncthreads();   // previous tile's reads done before restaging

            // stage audio tile (coalesced) + ids
            #pragma unroll
            for (int r = 0; r < 8; ++r) {
                const int e = tid + 256 * r;      // 0..2047
                a_s[e >> 6][e & 63] = audio[base * 64 + e];
            }
            if (tid < TILE_I)                 aid_s[tid]       = artist_ids[base + tid];
            else if (tid < 2 * TILE_I)        alid_s[tid - 32] = album_ids [base + tid - 32];
            __syncthreads();

            // GEMM: acc[m] = dot(a_s[8g+m][:], w_s[j][:])
            float acc[8] = {0.f, 0.f, 0.f, 0.f, 0.f, 0.f, 0.f, 0.f};
            const float* wrow = &w_s[j][0];
            #pragma unroll
            for (int kq = 0; kq < 16; ++kq) {
                const float4 w4 = *reinterpret_cast<const float4*>(wrow + kq * 4);
                #pragma unroll
                for (int m = 0; m < 8; ++m) {
                    const float4 a4 =
                        *reinterpret_cast<const float4*>(&a_s[g * 8 + m][kq * 4]);
                    acc[m] = fmaf(a4.x, w4.x, acc[m]);
                    acc[m] = fmaf(a4.y, w4.y, acc[m]);
                    acc[m] = fmaf(a4.z, w4.z, acc[m]);
                    acc[m] = fmaf(a4.w, w4.w, acc[m]);
                }
            }

            // epilogue: gather-add, store d, accumulate squared diff
            #pragma unroll
            for (int m = 0; m < 8; ++m) {
                const int   i  = g * 8 + m;
                const float a  = a_s[i][j];
                const float ar = artist_emb[aid_s[i]  * 64 + j];
                const float al = album_emb [alid_s[i] * 64 + j];
                const float d  = (a + ar + al) * 0.25f;
                item_out[(base + i) * 64 + j] = d;
                const float diff = d - acc[m];
                lsum = fmaf(diff, diff, lsum);
            }
        }

        // deterministic block reduction of the loss partial
        red[tid] = lsum;
        __syncthreads();
        #pragma unroll
        for (int off = 128; off > 0; off >>= 1) {
            if (tid < off) red[tid] += red[tid + off];
            __syncthreads();
        }
        if (tid == 0) g_partials[ibid] = red[0];
    } else {
        // ---------------- user path: scale-copy 32M floats ------------------
        const float4* in4  = reinterpret_cast<const float4*>(user_emb);
        float4*       out4 = reinterpret_cast<float4*>(out);
        const int n4     = USER_ELEMS / 4;                 // 8,000,000
        const int ubid   = blockIdx.x >> 1;                // 0..303
        const int stride = USER_BLOCKS * 256;              // 77,824
        int i = ubid * 256 + tid;

        for (; i + 3 * stride < n4; i += 4 * stride) {
            float4 v0 = in4[i];
            float4 v1 = in4[i +     stride];
            float4 v2 = in4[i + 2 * stride];
            float4 v3 = in4[i + 3 * stride];
            v0.x *= 0.25f; v0.y *= 0.25f; v0.z *= 0.25f; v0.w *= 0.25f;
            v1.x *= 0.25f; v1.y *= 0.25f; v1.z *= 0.25f; v1.w *= 0.25f;
            v2.x *= 0.25f; v2.y *= 0.25f; v2.z *= 0.25f; v2.w *= 0.25f;
            v3.x *= 0.25f; v3.y *= 0.25f; v3.z *= 0.25f; v3.w *= 0.25f;
            out4[i]              = v0;
            out4[i +     stride] = v1;
            out4[i + 2 * stride] = v2;
            out4[i + 3 * stride] = v3;
        }
        for (; i < n4; i += stride) {
            float4 v = in4[i];
            v.x *= 0.25f; v.y *= 0.25f; v.z *= 0.25f; v.w *= 0.25f;
            out4[i] = v;
        }
    }
}

__global__ void finalize_kernel(float* __restrict__ out)
{
    __shared__ float red[256];
    float s = 0.0f;
    for (int i = threadIdx.x; i < ITEM_BLOCKS; i += 256) s += g_partials[i];
    red[threadIdx.x] = s;
    __syncthreads();
    #pragma unroll
    for (int off = 128; off > 0; off >>= 1) {
        if (threadIdx.x < off) red[threadIdx.x] += red[threadIdx.x + off];
        __syncthreads();
    }
    if (threadIdx.x == 0)
        out[LOSS_IDX] = red[0] * (1.0f / (float)ITEM_ELEMS);
}

extern "C" void kernel_launch(void* const* d_in, const int* in_sizes, int n_in,
                              void* d_out, int out_size)
{
    const float* user_emb   = (const float*)d_in[0];
    const float* artist_emb = (const float*)d_in[1];
    const float* album_emb  = (const float*)d_in[2];
    const float* audio      = (const float*)d_in[3];
    const float* Wproj      = (const float*)d_in[4];
    // d_in[5..11]: mlp weights / edge data — dead (norm == 0 structurally)
    const int* artist_ids   = (const int*)d_in[12];
    const int* album_ids    = (const int*)d_in[13];
    float* out = (float*)d_out;

    fused_kernel<<<TOTAL_BLOCKS, 256>>>(user_emb, artist_emb, album_emb, audio,
                                        Wproj, artist_ids, album_ids, out);
    finalize_kernel<<<1, 256>>>(out);
}

// round 6
// speedup vs baseline: 1.4862x; 1.0727x over previous
#include <cuda_runtime.h>

// LightGCN_4440996184480 — structural simplification (verified rel_err=0):
// norm == 0 for all edges => all GCN layers zero.
//   out[0 : 32M)     = user_emb * 0.25
//   out[32M : 44.8M) = (audio + artist_emb[aid] + album_emb[alid]) * 0.25
//   out[44.8M]       = mean((item_h/4 - audio @ W^T)^2)
//
// R6: single persistent kernel (last-block loss finalize), streaming cache
// hints (keep gather tables in L2), dynamic copy work-queue (no tail
// imbalance), packed fma.rn.f32x2 dot product, 1 barrier per item tile.

#define NUM_USERS  500000
#define NUM_ITEMS  200000
#define USER_ELEMS (NUM_USERS * 64)          // 32,000,000
#define ITEM_ELEMS (NUM_ITEMS * 64)          // 12,800,000
#define LOSS_IDX   (USER_ELEMS + ITEM_ELEMS) // 44,800,000

#define ITEM_BLOCKS 304
#define TOTAL_BLOCKS 608
#define TILE_I 32

#define N4        (USER_ELEMS / 4)           // 8,000,000 float4
#define CHUNK_F4  1024                       // per warp-grab: 16 KB
#define NCHUNKS   ((N4 + CHUNK_F4 - 1) / CHUNK_F4)   // 7813

__device__ float        g_partials[ITEM_BLOCKS];
__device__ unsigned int g_item_done = 0;
__device__ unsigned int g_chunk     = 0;
__device__ unsigned int g_exit      = 0;

#define PK(out, lo, hi) \
    asm("mov.b64 %0, {%1, %2};" : "=l"(out) : "f"(lo), "f"(hi))
#define UPK(lo, hi, in) \
    asm("mov.b64 {%0, %1}, %2;" : "=f"(lo), "=f"(hi) : "l"(in))
#define FMA2(d, a, b, c) \
    asm("fma.rn.f32x2 %0, %1, %2, %3;" : "=l"(d) : "l"(a), "l"(b), "l"(c))

__global__ __launch_bounds__(256) void fused_kernel(
    const float* __restrict__ user_emb,
    const float* __restrict__ artist_emb,
    const float* __restrict__ album_emb,
    const float* __restrict__ audio,
    const float* __restrict__ Wproj,       // (64,64) row-major
    const int*   __restrict__ artist_ids,
    const int*   __restrict__ album_ids,
    float*       __restrict__ out)
{
    __shared__ float4 wq_s[16][64];        // W quad kq of row j at [kq][j]
    __shared__ float  a_s[2][TILE_I][64];  // ping-pong audio tiles
    __shared__ int    aid_s[2][TILE_I];
    __shared__ int    alid_s[2][TILE_I];
    __shared__ float  red[256];

    const int tid  = threadIdx.x;
    const int lane = tid & 31;

    if ((blockIdx.x & 1) == 0) {
        // ================= item path =====================================
        const int ibid = blockIdx.x >> 1;  // 0..303
        const int j    = tid & 63;         // output column
        const int g    = tid >> 6;         // item group: items 8g..8g+7

        // stage W transposed-by-quad (once; covered by first tile's barrier)
        #pragma unroll
        for (int r = 0; r < 16; ++r) {
            const int e = tid + 256 * r;   // e = j*64 + k over all 4096
            const int jr = e >> 6, k = e & 63;
            reinterpret_cast<float*>(&wq_s[k >> 2][jr])[k & 3] = Wproj[e];
        }

        float  lsum = 0.0f;
        float* item_out = out + USER_ELEMS;
        int    buf = 0;

        for (int base = ibid * TILE_I; base < NUM_ITEMS;
             base += ITEM_BLOCKS * TILE_I, buf ^= 1) {
            // stage audio tile (streaming loads) + ids
            #pragma unroll
            for (int r = 0; r < 8; ++r) {
                const int e = tid + 256 * r;
                a_s[buf][e >> 6][e & 63] = __ldcs(&audio[base * 64 + e]);
            }
            if (tid < TILE_I)          aid_s [buf][tid]      = artist_ids[base + tid];
            else if (tid < 2 * TILE_I) alid_s[buf][tid - 32] = album_ids [base + tid - 32];
            __syncthreads();           // single barrier per tile (ping-pong)

            // proj[m][j] = dot(a_s[8g+m], W[j]) with packed f32x2 FMA
            unsigned long long acc[8];
            #pragma unroll
            for (int m = 0; m < 8; ++m) acc[m] = 0ull;   // (+0.f, +0.f)

            #pragma unroll
            for (int kq = 0; kq < 16; ++kq) {
                const float4 w4 = wq_s[kq][j];           // conflict-free LDS.128
                unsigned long long wlo, whi;
                PK(wlo, w4.x, w4.y);
                PK(whi, w4.z, w4.w);
                #pragma unroll
                for (int m = 0; m < 8; ++m) {
                    const float4 a4 = *reinterpret_cast<const float4*>(
                        &a_s[buf][g * 8 + m][kq * 4]);   // broadcast LDS.128
                    unsigned long long alo, ahi;
                    PK(alo, a4.x, a4.y);
                    PK(ahi, a4.z, a4.w);
                    FMA2(acc[m], alo, wlo, acc[m]);
                    FMA2(acc[m], ahi, whi, acc[m]);
                }
            }

            // epilogue: gather-add (L2-cached tables), streaming store, loss
            #pragma unroll
            for (int m = 0; m < 8; ++m) {
                const int   i  = g * 8 + m;
                const float a  = a_s[buf][i][j];
                const float ar = artist_emb[aid_s [buf][i] * 64 + j];
                const float al = album_emb [alid_s[buf][i] * 64 + j];
                const float d  = (a + ar + al) * 0.25f;
                __stcs(&item_out[(base + i) * 64 + j], d);
                float plo, phi;
                UPK(plo, phi, acc[m]);
                const float diff = d - (plo + phi);
                lsum = fmaf(diff, diff, lsum);
            }
        }

        // deterministic block reduction of the loss partial
        red[tid] = lsum;
        __syncthreads();
        #pragma unroll
        for (int off = 128; off > 0; off >>= 1) {
            if (tid < off) red[tid] += red[tid + off];
            __syncthreads();
        }
        if (tid == 0) {
            g_partials[ibid] = red[0];
            __threadfence();
            const unsigned old = atomicAdd(&g_item_done, 1u);
            if (old == ITEM_BLOCKS - 1) {      // last item block: finalize
                __threadfence();
                float s = 0.0f;
                for (int i = 0; i < ITEM_BLOCKS; ++i) s += g_partials[i];
                out[LOSS_IDX] = s * (1.0f / (float)ITEM_ELEMS);
                g_item_done = 0;               // reset for next graph replay
            }
        }
        // fall through: help with the copy queue
    }

    // ================= user copy: dynamic warp work-queue ================
    {
        const float4* in4  = reinterpret_cast<const float4*>(user_emb);
        float4*       out4 = reinterpret_cast<float4*>(out);

        unsigned c;
        if (lane == 0) c = atomicAdd(&g_chunk, 1u);
        c = __shfl_sync(0xffffffffu, c, 0);
        while (c < NCHUNKS) {
            const int b = (int)c * CHUNK_F4;
            #pragma unroll
            for (int r = 0; r < CHUNK_F4 / 32; ++r) {
                const int i = b + r * 32 + lane;
                if (i < N4) {
                    float4 v = __ldcs(&in4[i]);
                    v.x *= 0.25f; v.y *= 0.25f; v.z *= 0.25f; v.w *= 0.25f;
                    __stcs(&out4[i], v);
                }
            }
            if (lane == 0) c = atomicAdd(&g_chunk, 1u);
            c = __shfl_sync(0xffffffffu, c, 0);
        }
    }

    // ================= counter reset for graph replay ====================
    __syncthreads();
    if (tid == 0) {
        const unsigned old = atomicAdd(&g_exit, 1u);
        if (old == TOTAL_BLOCKS - 1) {   // very last block: reset queue
            g_chunk = 0;
            g_exit  = 0;
        }
    }
}

extern "C" void kernel_launch(void* const* d_in, const int* in_sizes, int n_in,
                              void* d_out, int out_size)
{
    const float* user_emb   = (const float*)d_in[0];
    const float* artist_emb = (const float*)d_in[1];
    const float* album_emb  = (const float*)d_in[2];
    const float* audio      = (const float*)d_in[3];
    const float* Wproj      = (const float*)d_in[4];
    // d_in[5..11]: mlp weights / edge data — dead (norm == 0 structurally)
    const int* artist_ids   = (const int*)d_in[12];
    const int* album_ids    = (const int*)d_in[13];
    float* out = (float*)d_out;

    fused_kernel<<<TOTAL_BLOCKS, 256>>>(user_emb, artist_emb, album_emb, audio,
                                        Wproj, artist_ids, album_ids, out);
}

// round 7
// speedup vs baseline: 1.5739x; 1.0590x over previous
#include <cuda_runtime.h>

// LightGCN_4440996184480 — structural simplification (verified rel_err=0):
// norm == 0 for all edges => all GCN layers zero.
//   out[0 : 32M)     = user_emb * 0.25
//   out[32M : 44.8M) = (audio + artist_emb[aid] + album_emb[alid]) * 0.25
//   out[44.8M]       = mean((item_h/4 - audio @ W^T)^2)
//
// R6: single persistent kernel (last-block loss finalize), streaming cache
// hints (keep gather tables in L2), dynamic copy work-queue (no tail
// imbalance), packed fma.rn.f32x2 dot product, 1 barrier per item tile.

#define NUM_USERS  500000
#define NUM_ITEMS  200000
#define USER_ELEMS (NUM_USERS * 64)          // 32,000,000
#define ITEM_ELEMS (NUM_ITEMS * 64)          // 12,800,000
#define LOSS_IDX   (USER_ELEMS + ITEM_ELEMS) // 44,800,000

#define ITEM_BLOCKS 304
#define TOTAL_BLOCKS 608
#define TILE_I 32

#define N4        (USER_ELEMS / 4)           // 8,000,000 float4
#define CHUNK_F4  1024                       // per warp-grab: 16 KB
#define NCHUNKS   ((N4 + CHUNK_F4 - 1) / CHUNK_F4)   // 7813

__device__ float        g_partials[ITEM_BLOCKS];
__device__ unsigned int g_item_done = 0;
__device__ unsigned int g_chunk     = 0;
__device__ unsigned int g_exit      = 0;

#define PK(out, lo, hi) \
    asm("mov.b64 %0, {%1, %2};" : "=l"(out) : "f"(lo), "f"(hi))
#define UPK(lo, hi, in) \
    asm("mov.b64 {%0, %1}, %2;" : "=f"(lo), "=f"(hi) : "l"(in))
#define FMA2(d, a, b, c) \
    asm("fma.rn.f32x2 %0, %1, %2, %3;" : "=l"(d) : "l"(a), "l"(b), "l"(c))

__global__ __launch_bounds__(256) void fused_kernel(
    const float* __restrict__ user_emb,
    const float* __restrict__ artist_emb,
    const float* __restrict__ album_emb,
    const float* __restrict__ audio,
    const float* __restrict__ Wproj,       // (64,64) row-major
    const int*   __restrict__ artist_ids,
    const int*   __restrict__ album_ids,
    float*       __restrict__ out)
{
    __shared__ float4 wq_s[16][64];        // W quad kq of row j at [kq][j]
    __shared__ float  a_s[2][TILE_I][64];  // ping-pong audio tiles
    __shared__ int    aid_s[2][TILE_I];
    __shared__ int    alid_s[2][TILE_I];
    __shared__ float  red[256];

    const int tid  = threadIdx.x;
    const int lane = tid & 31;

    if ((blockIdx.x & 1) == 0) {
        // ================= item path =====================================
        const int ibid = blockIdx.x >> 1;  // 0..303
        const int j    = tid & 63;         // output column
        const int g    = tid >> 6;         // item group: items 8g..8g+7

        // stage W transposed-by-quad (once; covered by first tile's barrier)
        #pragma unroll
        for (int r = 0; r < 16; ++r) {
            const int e = tid + 256 * r;   // e = j*64 + k over all 4096
            const int jr = e >> 6, k = e & 63;
            reinterpret_cast<float*>(&wq_s[k >> 2][jr])[k & 3] = Wproj[e];
        }

        float  lsum = 0.0f;
        float* item_out = out + USER_ELEMS;
        int    buf = 0;

        for (int base = ibid * TILE_I; base < NUM_ITEMS;
             base += ITEM_BLOCKS * TILE_I, buf ^= 1) {
            // stage audio tile (streaming loads) + ids
            #pragma unroll
            for (int r = 0; r < 8; ++r) {
                const int e = tid + 256 * r;
                a_s[buf][e >> 6][e & 63] = __ldcs(&audio[base * 64 + e]);
            }
            if (tid < TILE_I)          aid_s [buf][tid]      = artist_ids[base + tid];
            else if (tid < 2 * TILE_I) alid_s[buf][tid - 32] = album_ids [base + tid - 32];
            __syncthreads();           // single barrier per tile (ping-pong)

            // proj[m][j] = dot(a_s[8g+m], W[j]) with packed f32x2 FMA
            unsigned long long acc[8];
            #pragma unroll
            for (int m = 0; m < 8; ++m) acc[m] = 0ull;   // (+0.f, +0.f)

            #pragma unroll
            for (int kq = 0; kq < 16; ++kq) {
                const float4 w4 = wq_s[kq][j];           // conflict-free LDS.128
                unsigned long long wlo, whi;
                PK(wlo, w4.x, w4.y);
                PK(whi, w4.z, w4.w);
                #pragma unroll
                for (int m = 0; m < 8; ++m) {
                    const float4 a4 = *reinterpret_cast<const float4*>(
                        &a_s[buf][g * 8 + m][kq * 4]);   // broadcast LDS.128
                    unsigned long long alo, ahi;
                    PK(alo, a4.x, a4.y);
                    PK(ahi, a4.z, a4.w);
                    FMA2(acc[m], alo, wlo, acc[m]);
                    FMA2(acc[m], ahi, whi, acc[m]);
                }
            }

            // epilogue: gather-add (L2-cached tables), streaming store, loss
            #pragma unroll
            for (int m = 0; m < 8; ++m) {
                const int   i  = g * 8 + m;
                const float a  = a_s[buf][i][j];
                const float ar = artist_emb[aid_s [buf][i] * 64 + j];
                const float al = album_emb [alid_s[buf][i] * 64 + j];
                const float d  = (a + ar + al) * 0.25f;
                __stcs(&item_out[(base + i) * 64 + j], d);
                float plo, phi;
                UPK(plo, phi, acc[m]);
                const float diff = d - (plo + phi);
                lsum = fmaf(diff, diff, lsum);
            }
        }

        // deterministic block reduction of the loss partial
        red[tid] = lsum;
        __syncthreads();
        #pragma unroll
        for (int off = 128; off > 0; off >>= 1) {
            if (tid < off) red[tid] += red[tid + off];
            __syncthreads();
        }
        if (tid == 0) {
            g_partials[ibid] = red[0];
            __threadfence();
            const unsigned old = atomicAdd(&g_item_done, 1u);
            if (old == ITEM_BLOCKS - 1) {      // last item block: finalize
                __threadfence();
                float s = 0.0f;
                for (int i = 0; i < ITEM_BLOCKS; ++i) s += g_partials[i];
                out[LOSS_IDX] = s * (1.0f / (float)ITEM_ELEMS);
                g_item_done = 0;               // reset for next graph replay
            }
        }
        // fall through: help with the copy queue
    }

    // ================= user copy: dynamic warp work-queue ================
    {
        const float4* in4  = reinterpret_cast<const float4*>(user_emb);
        float4*       out4 = reinterpret_cast<float4*>(out);

        unsigned c;
        if (lane == 0) c = atomicAdd(&g_chunk, 1u);
        c = __shfl_sync(0xffffffffu, c, 0);
        while (c < NCHUNKS) {
            const int b = (int)c * CHUNK_F4;
            #pragma unroll
            for (int r = 0; r < CHUNK_F4 / 32; ++r) {
                const int i = b + r * 32 + lane;
                if (i < N4) {
                    float4 v = __ldcs(&in4[i]);
                    v.x *= 0.25f; v.y *= 0.25f; v.z *= 0.25f; v.w *= 0.25f;
                    __stcs(&out4[i], v);
                }
            }
            if (lane == 0) c = atomicAdd(&g_chunk, 1u);
            c = __shfl_sync(0xffffffffu, c, 0);
        }
    }

    // ================= counter reset for graph replay ====================
    __syncthreads();
    if (tid == 0) {
        const unsigned old = atomicAdd(&g_exit, 1u);
        if (old == TOTAL_BLOCKS - 1) {   // very last block: reset queue
            g_chunk = 0;
            g_exit  = 0;
        }
    }
}

extern "C" void kernel_launch(void* const* d_in, const int* in_sizes, int n_in,
                              void* d_out, int out_size)
{
    const float* user_emb   = (const float*)d_in[0];
    const float* artist_emb = (const float*)d_in[1];
    const float* album_emb  = (const float*)d_in[2];
    const float* audio      = (const float*)d_in[3];
    const float* Wproj      = (const float*)d_in[4];
    // d_in[5..11]: mlp weights / edge data — dead (norm == 0 structurally)
    const int* artist_ids   = (const int*)d_in[12];
    const int* album_ids    = (const int*)d_in[13];
    float* out = (float*)d_out;

    fused_kernel<<<TOTAL_BLOCKS, 256>>>(user_emb, artist_emb, album_emb, audio,
                                        Wproj, artist_ids, album_ids, out);
}